// round 11
// baseline (speedup 1.0000x reference)
#include <cuda_runtime.h>
#include <cstdint>

#define NEG   (-1e30f)
#define LOG2E (1.4426950408889634f)
#define LN2   (0.6931471805599453f)
#define FULLMASK 0xffffffffu

// Fixed problem shape (B=32, T=1024, V=1000, L=128); scratch sized to max.
#define MAXB 32
#define MAXT 1024
#define MAXL 128
#define ESTR 132     // padded emission row stride (floats): 129 used
#define CH   8       // timesteps per SMEM chunk == levels per superstep
#define CHF  (CH * ESTR)        // floats per chunk (1056)
#define CHV  (CHF / 4)          // float4 per chunk (264)
#define HALO 16
#define ABUFN 296    // alpha buffer padded so all (masked) halo reads stay in-bounds

// Static scratch (no allocation allowed anywhere).
__device__ float g_emit[(size_t)MAXB * MAXT * ESTR];
__device__ float g_res[MAXB];

__device__ __forceinline__ float ex2a(float x) {
    float r; asm("ex2.approx.ftz.f32 %0, %1;" : "=f"(r) : "f"(x)); return r;
}
__device__ __forceinline__ float lg2a(float x) {
    float r; asm("lg2.approx.ftz.f32 %0, %1;" : "=f"(r) : "f"(x)); return r;
}
__device__ __forceinline__ float lse3_2(float a, float b, float c) {
    // logsumexp in log2 domain: m + log2(2^(a-m)+2^(b-m)+2^(c-m))
    float m = fmaxf(a, fmaxf(b, c));
    float s = ex2a(a - m) + ex2a(b - m) + ex2a(c - m);
    return m + lg2a(s);
}

// ---------------------------------------------------------------------------
// Kernel A: one WARP per (b,t) row. Single pass over V=1000 in registers,
// warp-shuffle reductions only. Emits log2-domain log-softmax for the 129
// needed tokens (blank + L labels) into g_emit.
// ---------------------------------------------------------------------------
__global__ void __launch_bounds__(128) lse_gather_kernel(
    const float* __restrict__ pred,
    const int*   __restrict__ target,
    int T, int V, int L, int nrows)
{
    const int warp = blockIdx.x * (blockDim.x >> 5) + (threadIdx.x >> 5);
    if (warp >= nrows) return;
    const int lane = threadIdx.x & 31;
    const int b = warp / T;

    const float* __restrict__ row = pred + (size_t)warp * V;
    const float4* __restrict__ row4 = (const float4*)row;
    const int nvec = V >> 2;     // 250

    float4 v[8];
    #pragma unroll
    for (int i = 0; i < 8; ++i) {
        const int idx = lane + (i << 5);
        v[i] = (idx < nvec) ? row4[idx] : make_float4(NEG, NEG, NEG, NEG);
    }

    float m = NEG;
    #pragma unroll
    for (int i = 0; i < 8; ++i)
        m = fmaxf(m, fmaxf(fmaxf(v[i].x, v[i].y), fmaxf(v[i].z, v[i].w)));
    #pragma unroll
    for (int o = 16; o > 0; o >>= 1) m = fmaxf(m, __shfl_xor_sync(FULLMASK, m, o));

    const float m2 = m * LOG2E;
    float sum = 0.f;
    #pragma unroll
    for (int i = 0; i < 8; ++i) {
        sum += ex2a(fmaf(v[i].x, LOG2E, -m2)) + ex2a(fmaf(v[i].y, LOG2E, -m2))
             + ex2a(fmaf(v[i].z, LOG2E, -m2)) + ex2a(fmaf(v[i].w, LOG2E, -m2));
    }
    #pragma unroll
    for (int o = 16; o > 0; o >>= 1) sum += __shfl_xor_sync(FULLMASK, sum, o);

    const float lse2 = m2 + lg2a(sum);   // log2(sum_v exp(x_v))

    float* __restrict__ erow = g_emit + (size_t)warp * ESTR;
    const int* __restrict__ tgt = target + (size_t)b * L;
    for (int j = lane; j <= L; j += 32) {
        const int tok = (j == 0) ? 0 : tgt[j - 1];
        erow[j] = fmaf(row[tok], LOG2E, -lse2);
    }
}

// ---------------------------------------------------------------------------
// Kernel B: W-CTC forward DP, one block per batch, one thread per state
// (288 thr, 9 warps). K=8 REGISTER TRAPEZOID: each warp keeps its state x and
// a 16-state halo y (states base-16..base-1, warp w-1's top) in registers and
// advances 8 levels per __syncthreads via shfl_up; the halo narrows 2/level
// (16 halo = exactly 8 levels). Shared traffic per superstep: STS x, LDS y,
// 16 emission LDS (preloaded to regs). Emission chunks (8 rows) staged
// through a double-buffered SMEM pipeline fed by LDG one superstep ahead.
// endstar absorbed in-register by the warp owning state ll.
// ---------------------------------------------------------------------------
__global__ void __launch_bounds__(288) wctc_dp_kernel(
    const int* __restrict__ target,
    const int* __restrict__ tlen,
    int T, int L)
{
    const int b    = blockIdx.x;
    const int tid  = threadIdx.x;
    const int lane = tid & 31;
    const int w    = tid >> 5;
    const int base = w << 5;

    __shared__ float abuf[2][ABUFN];     // alpha at superstep boundaries; idx s+2
    __shared__ float e_sh[2][CHF];       // staged emission chunks
    __shared__ int   tg[MAXL];

    for (int k = tid; k < L; k += 288) tg[k] = target[(size_t)b * L + k];
    __syncthreads();

    const int  tl    = tlen[b];
    const int  s     = tid;
    const bool odd   = (s & 1) != 0;
    const bool valid = (s <= 2 * tl + 1);
    bool skipOK = false;
    if (!odd && s >= 2 && s < 2 * L + 2)
        skipOK = (s == 2) || (tg[(s >> 1) - 1] != tg[(s >> 1) - 2]);
    int j = odd ? 0 : (s >> 1);
    if (j > L) j = 0;                    // clamp inactive-thread column

    // Halo state owned by this lane (w>0): sy in [base-16, base+15], sy>=16.
    const int  sy    = base - HALO + lane;
    const bool hOdd  = (sy & 1) != 0;
    const bool hValid = (sy <= 2 * tl + 1);
    int jh = hOdd ? 0 : (sy >> 1);
    if (jh > L) jh = 0;
    bool hSkip = false;
    if (w > 0 && !hOdd) hSkip = (tg[(sy >> 1) - 1] != tg[(sy >> 1) - 2]);

    const int  ll    = 2 * tl;
    const bool owner = (w == (ll >> 5));
    const int  lOwn  = ll & 31;

    const float*  __restrict__ erow  = g_emit + (size_t)b * T * ESTR;
    const float4* __restrict__ erow4 = (const float4*)erow;

    // ---- level 0 init (x in register) ----
    float x;
    if (s == 0)      x = 0.f;
    else if (s == 1) x = erow[0];
    else if (s == 2) x = erow[1];
    else             x = NEG;
    if (!valid)      x = NEG;
    float y  = NEG;
    float es = NEG;

    // Preload chunk 0
    float4 ld = make_float4(NEG, NEG, NEG, NEG);
    if (tid < CHV) ld = erow4[tid];

#define LEVEL(EX, EY) do {                                                    \
    if (owner) {                         /* absorb alpha_{t-1}[ll],[lb] */    \
        float xdn = __shfl_down_sync(FULLMASK, x, 1);                         \
        if (lane == lOwn) es = lse3_2(es, x, xdn);                            \
    }                                                                         \
    float xn1 = __shfl_up_sync(FULLMASK, x, 1);                               \
    float xn2 = __shfl_up_sync(FULLMASK, x, 2);                               \
    float y15 = NEG, y14 = NEG, ny = NEG;                                     \
    if (w > 0) {                                                              \
        y15 = __shfl_sync(FULLMASK, y, 15);                                   \
        y14 = __shfl_sync(FULLMASK, y, 14);                                   \
        float yn1 = __shfl_up_sync(FULLMASK, y, 1);                           \
        float yn2 = __shfl_up_sync(FULLMASK, y, 2);                           \
        ny = (EY) + lse3_2(y, yn1, hSkip ? yn2 : NEG);                        \
        if (!hValid) ny = NEG;                                                \
    }                                                                         \
    if (lane == 0)      { xn1 = y15; xn2 = y14; }                             \
    else if (lane == 1) { xn2 = y15; }                                        \
    float nx = (EX) + lse3_2(x, xn1, skipOK ? xn2 : NEG);                     \
    if (s == 0) nx = x;                  /* star: self-loop, emission 0 */    \
    if (!valid) nx = NEG;                                                     \
    x = nx;                                                                   \
    if (w > 0) y = ny;                                                        \
} while (0)

    const int nchunks = T / CH;          // 128 supersteps

    // ---- superstep 0: levels 1..7 ----
    {
        if (tid < CHV) ((float4*)e_sh[0])[tid] = ld;
        if (tid < CHV) ld = erow4[(size_t)CHV + tid];
        abuf[0][s + 2] = x;
        __syncthreads();
        if (w > 0) y = abuf[0][base - HALO + lane + 2];
        const float* __restrict__ E = e_sh[0];
        float exv[CH], eyv[CH];
        #pragma unroll
        for (int m = 1; m < CH; ++m) exv[m] = E[m * ESTR + j];
        if (w > 0) {
            #pragma unroll
            for (int m = 1; m < CH; ++m) eyv[m] = E[m * ESTR + jh];
        }
        #pragma unroll
        for (int m = 1; m < CH; ++m) LEVEL(exv[m], eyv[m]);
    }

    // ---- supersteps 1..127: levels 8c..8c+7 ----
    for (int c = 1; c < nchunks; ++c) {
        const int pb = c & 1;
        if (tid < CHV) ((float4*)e_sh[pb])[tid] = ld;
        if (c + 1 < nchunks && tid < CHV)
            ld = erow4[(size_t)(c + 1) * CHV + tid];
        abuf[pb][s + 2] = x;
        __syncthreads();
        if (w > 0) y = abuf[pb][base - HALO + lane + 2];
        const float* __restrict__ E = e_sh[pb];
        float exv[CH], eyv[CH];
        #pragma unroll
        for (int m = 0; m < CH; ++m) exv[m] = E[m * ESTR + j];
        if (w > 0) {
            #pragma unroll
            for (int m = 0; m < CH; ++m) eyv[m] = E[m * ESTR + jh];
        }
        #pragma unroll
        for (int m = 0; m < CH; ++m) LEVEL(exv[m], eyv[m]);
    }

#undef LEVEL

    // ---- finalize: total = lse3(alpha_{T-1}[ll], alpha_{T-1}[lb], endstar) ----
    if (owner) {
        float xdn = __shfl_down_sync(FULLMASK, x, 1);
        if (lane == lOwn) {
            const float tot2 = lse3_2(x, xdn, es);
            g_res[b] = (-tot2 * LN2) / (float)tl;    // nll / target_length
        }
    }
}

// ---------------------------------------------------------------------------
// Kernel C: mean over batch -> scalar output.
// ---------------------------------------------------------------------------
__global__ void __launch_bounds__(32) finalize_kernel(float* __restrict__ out, int B)
{
    float v = 0.f;
    for (int i = threadIdx.x; i < B; i += 32) v += g_res[i];
    #pragma unroll
    for (int o = 16; o > 0; o >>= 1) v += __shfl_xor_sync(FULLMASK, v, o);
    if (threadIdx.x == 0) out[0] = v / (float)B;
}

extern "C" void kernel_launch(void* const* d_in, const int* in_sizes, int n_in,
                              void* d_out, int out_size)
{
    const float* pred   = (const float*)d_in[0];   // (B,T,V) fp32
    const int*   target = (const int*)d_in[1];     // (B,L)  int32
    const int*   tlen   = (const int*)d_in[2];     // (B,)   int32

    const int B = in_sizes[2];
    const int L = in_sizes[1] / B;
    const int V = 1000;
    const int T = in_sizes[0] / (B * V);
    const int nrows = B * T;

    lse_gather_kernel<<<(nrows + 3) / 4, 128>>>(pred, target, T, V, L, nrows);
    wctc_dp_kernel<<<B, 288>>>(target, tlen, T, L);
    finalize_kernel<<<1, 32>>>((float*)d_out, B);
}